// round 1
// baseline (speedup 1.0000x reference)
#include <cuda_runtime.h>
#include <cuda_bf16.h>
#include <math.h>

// Problem constants (fixed by setup_inputs)
#define B_    2
#define Q_    12240
#define E_    256
#define H_    8
#define L_    4
#define KP_   4
#define HD_   32
#define VLEN_ 12240
#define BQ_   (B_ * Q_)      // 24480
#define BV_   (B_ * VLEN_)   // 24480

// Scratch (static __device__ — no allocation)
__device__ float g_vproj[(size_t)BV_ * E_];        // (B, Vlen, H*hd)  25 MB
__device__ float g_offlog[(size_t)BQ_ * 256];      // offset logits    25 MB
__device__ float g_attnlog[(size_t)BQ_ * 128];     // attn logits      12.5 MB
__device__ float g_locs[(size_t)BQ_ * 256];        // (bq, h,l,k,c)    25 MB
__device__ float g_attnw[(size_t)BQ_ * 128];       // (bq, h,l,k)      12.5 MB
__device__ float g_acc[(size_t)BQ_ * E_];          // sampled output   25 MB

// ---------------------------------------------------------------------------
// Generic fp32 SGEMM: C[M,N] = A[M,K] * B[K,N], row-major. 64x64 tile, 4x4/thr.
// ---------------------------------------------------------------------------
#define TM 64
#define TN 64
#define TK 16

__global__ void sgemm64(const float* __restrict__ A, const float* __restrict__ Bm,
                        float* __restrict__ C, int M, int N, int K) {
    __shared__ float As[TK][TM];
    __shared__ float Bs[TK][TN];
    const int tx = threadIdx.x;           // 0..15
    const int ty = threadIdx.y;           // 0..15
    const int tid = ty * 16 + tx;         // 0..255
    const int bm = blockIdx.y * TM;
    const int bn = blockIdx.x * TN;

    float acc[4][4];
#pragma unroll
    for (int i = 0; i < 4; i++)
#pragma unroll
        for (int j = 0; j < 4; j++) acc[i][j] = 0.f;

    for (int k0 = 0; k0 < K; k0 += TK) {
        // Stage A tile: 64 rows x 16 k  (1024 elems / 256 threads = 4 each)
#pragma unroll
        for (int i = 0; i < 4; i++) {
            int idx = tid * 4 + i;
            int r = idx / TK;
            int kk = idx % TK;
            int gr = bm + r;
            float v = 0.f;
            if (gr < M) v = A[(size_t)gr * K + k0 + kk];
            As[kk][r] = v;
        }
        // Stage B tile: 16 k x 64 cols
#pragma unroll
        for (int i = 0; i < 4; i++) {
            int idx = tid * 4 + i;
            int kk = idx / TN;
            int c = idx % TN;
            Bs[kk][c] = Bm[(size_t)(k0 + kk) * N + bn + c];
        }
        __syncthreads();
#pragma unroll
        for (int kk = 0; kk < TK; kk++) {
            float a[4], b[4];
#pragma unroll
            for (int i = 0; i < 4; i++) a[i] = As[kk][ty * 4 + i];
#pragma unroll
            for (int j = 0; j < 4; j++) b[j] = Bs[kk][tx * 4 + j];
#pragma unroll
            for (int i = 0; i < 4; i++)
#pragma unroll
                for (int j = 0; j < 4; j++) acc[i][j] += a[i] * b[j];
        }
        __syncthreads();
    }
#pragma unroll
    for (int i = 0; i < 4; i++) {
        int gr = bm + ty * 4 + i;
        if (gr < M) {
#pragma unroll
            for (int j = 0; j < 4; j++)
                C[(size_t)gr * N + bn + tx * 4 + j] = acc[i][j];
        }
    }
}

// ---------------------------------------------------------------------------
// Postprocess: tanh offsets + ref + clamp -> locs; per-head softmax -> weights
// One block (256 threads) per query row (bq).
// ---------------------------------------------------------------------------
__global__ void postproc(const float* __restrict__ offlog,
                         const float* __restrict__ attnlog,
                         const float* __restrict__ ref,
                         const float* __restrict__ boff,
                         const float* __restrict__ battn,
                         float* __restrict__ locs,
                         float* __restrict__ attnw) {
    const int bq = blockIdx.x;
    const int t = threadIdx.x;      // 0..255
    __shared__ float sm[128];

    // locs: j = ((h*L + l)*K + k)*2 + c  = h*32 + (l*4+k)*2 + c
    {
        float off = tanhf(offlog[(size_t)bq * 256 + t] + boff[t]);
        int rem = t & 31;
        int l = rem >> 3;
        int c = t & 1;
        float r = ref[(size_t)bq * (L_ * 2) + l * 2 + c];
        float v = r + off;
        v = fminf(fmaxf(v, -1.f), 1.f);
        locs[(size_t)bq * 256 + t] = v;
    }
    if (t < 128) sm[t] = attnlog[(size_t)bq * 128 + t] + battn[t];
    __syncthreads();
    if (t < 8) {   // one thread per head: softmax over its 16 (l,k) logits
        float mx = -1e30f;
#pragma unroll
        for (int i = 0; i < 16; i++) mx = fmaxf(mx, sm[t * 16 + i]);
        float e[16];
        float s = 0.f;
#pragma unroll
        for (int i = 0; i < 16; i++) { e[i] = expf(sm[t * 16 + i] - mx); s += e[i]; }
        float inv = 1.f / s;
#pragma unroll
        for (int i = 0; i < 16; i++)
            attnw[(size_t)bq * 128 + t * 16 + i] = e[i] * inv;
    }
}

// ---------------------------------------------------------------------------
// Deformable sampling: one warp per (bq, h); lane = channel d (0..31).
// vproj layout (b, p, h*32+d): a corner fetch is 32 lanes * 4B = 128B coalesced.
// ---------------------------------------------------------------------------
__global__ void sample_kernel(const float* __restrict__ vproj,
                              const float* __restrict__ locs,
                              const float* __restrict__ attnw,
                              const int* __restrict__ shapes,
                              float* __restrict__ acc) {
    const int gwarp = (blockIdx.x * blockDim.x + threadIdx.x) >> 5;
    const int lane = threadIdx.x & 31;
    if (gwarp >= BQ_ * H_) return;
    const int h = gwarp & 7;
    const int bq = gwarp >> 3;
    const int b = bq / Q_;

    const size_t locbase = (size_t)bq * 256 + h * 32;
    const size_t wbase = (size_t)bq * 128 + h * 16;
    const float* vb = vproj + (size_t)b * VLEN_ * E_ + h * HD_ + lane;

    float a = 0.f;
    int start = 0;
#pragma unroll
    for (int l = 0; l < L_; l++) {
        const int Hl = shapes[l * 2 + 0];
        const int Wl = shapes[l * 2 + 1];
        const float* p = vb + (size_t)start * E_;
#pragma unroll
        for (int k = 0; k < KP_; k++) {
            float w = __ldg(&attnw[wbase + l * 4 + k]);
            float lx = __ldg(&locs[locbase + (l * 4 + k) * 2 + 0]);
            float ly = __ldg(&locs[locbase + (l * 4 + k) * 2 + 1]);
            float x = (lx + 1.f) * 0.5f * (float)(Wl - 1);
            float y = (ly + 1.f) * 0.5f * (float)(Hl - 1);
            float x0f = floorf(x), y0f = floorf(y);
            float wx = x - x0f, wy = y - y0f;
            int x0 = min(max((int)x0f, 0), Wl - 1);
            int x1 = min(x0 + 1, Wl - 1);
            int y0 = min(max((int)y0f, 0), Hl - 1);
            int y1 = min(y0 + 1, Hl - 1);
            float v00 = p[(size_t)(y0 * Wl + x0) * E_];
            float v01 = p[(size_t)(y0 * Wl + x1) * E_];
            float v10 = p[(size_t)(y1 * Wl + x0) * E_];
            float v11 = p[(size_t)(y1 * Wl + x1) * E_];
            float v = (1.f - wy) * ((1.f - wx) * v00 + wx * v01)
                    + wy * ((1.f - wx) * v10 + wx * v11);
            a = fmaf(w, v, a);
        }
        start += Hl * Wl;
    }
    acc[(size_t)bq * E_ + h * HD_ + lane] = a;
}

// ---------------------------------------------------------------------------
extern "C" void kernel_launch(void* const* d_in, const int* in_sizes, int n_in,
                              void* d_out, int out_size) {
    const float* queries = (const float*)d_in[0];   // (B,Q,E)
    const float* ref     = (const float*)d_in[1];   // (B,Q,L,2)
    const float* value   = (const float*)d_in[2];   // (B,Vlen,E)
    const float* Wv      = (const float*)d_in[3];   // (E,E)
    const float* Woff    = (const float*)d_in[4];   // (E,256)
    const float* boff    = (const float*)d_in[5];   // (256,)
    const float* Wattn   = (const float*)d_in[6];   // (E,128)
    const float* battn   = (const float*)d_in[7];   // (128,)
    const float* Wout    = (const float*)d_in[8];   // (E,E)
    const int*   shapes  = (const int*)d_in[9];     // (L,2)
    float* out = (float*)d_out;

    float *vproj, *offlog, *attnlog, *locs, *attnw, *acc;
    cudaGetSymbolAddress((void**)&vproj,  g_vproj);
    cudaGetSymbolAddress((void**)&offlog, g_offlog);
    cudaGetSymbolAddress((void**)&attnlog, g_attnlog);
    cudaGetSymbolAddress((void**)&locs,   g_locs);
    cudaGetSymbolAddress((void**)&attnw,  g_attnw);
    cudaGetSymbolAddress((void**)&acc,    g_acc);

    dim3 blk(16, 16);

    // 1) value projection: (BV, 256) @ (256, 256)
    {
        dim3 grid(E_ / TN, (BV_ + TM - 1) / TM);
        sgemm64<<<grid, blk>>>(value, Wv, vproj, BV_, E_, E_);
    }
    // 2) offset logits: (BQ, 256) @ (256, 256)
    {
        dim3 grid(256 / TN, (BQ_ + TM - 1) / TM);
        sgemm64<<<grid, blk>>>(queries, Woff, offlog, BQ_, 256, E_);
    }
    // 3) attn logits: (BQ, 256) @ (256, 128)
    {
        dim3 grid(128 / TN, (BQ_ + TM - 1) / TM);
        sgemm64<<<grid, blk>>>(queries, Wattn, attnlog, BQ_, 128, E_);
    }
    // 4) tanh/ref/clamp + softmax
    postproc<<<BQ_, 256>>>(offlog, attnlog, ref, boff, battn, locs, attnw);

    // 5) deformable bilinear sampling + weighted accumulation
    {
        int total_threads = BQ_ * H_ * 32;
        sample_kernel<<<(total_threads + 255) / 256, 256>>>(vproj, locs, attnw, shapes, acc);
    }
    // 6) output projection: (BQ, 256) @ (256, 256) -> d_out
    {
        dim3 grid(E_ / TN, (BQ_ + TM - 1) / TM);
        sgemm64<<<grid, blk>>>(acc, Wout, out, BQ_, E_, E_);
    }
}

// round 3
// speedup vs baseline: 1.5165x; 1.5165x over previous
#include <cuda_runtime.h>
#include <cuda_bf16.h>
#include <math.h>

// Problem constants (fixed by setup_inputs)
#define B_    2
#define Q_    12240
#define E_    256
#define H_    8
#define L_    4
#define KP_   4
#define HD_   32
#define VLEN_ 12240
#define BQ_   (B_ * Q_)      // 24480
#define BV_   (B_ * VLEN_)   // 24480

// Scratch (static __device__ — no allocation)
__device__ float g_vproj[(size_t)BV_ * E_];
__device__ float g_offlog[(size_t)BQ_ * 256];
__device__ float g_attnlog[(size_t)BQ_ * 128];
__device__ float g_locs[(size_t)BQ_ * 256];
__device__ float g_attnw[(size_t)BQ_ * 128];
__device__ float g_acc[(size_t)BQ_ * E_];

// ---------------------------------------------------------------------------
// 3xTF32 tensor-core GEMM: C = A * B, row-major fp32 in/out, fp32-accurate.
// Each operand split v = hi + lo (both tf32); accumulate lo*hi + hi*lo + hi*hi.
// Block tile 128x128x32, 8 warps, warp tile 64x32, mma.m16n8k8.
// Requires: K % 32 == 0, N % 128 == 0.
// ---------------------------------------------------------------------------
__device__ __forceinline__ void split_tf32(float v, unsigned& hi, unsigned& lo) {
    unsigned h;
    asm("cvt.rna.tf32.f32 %0, %1;" : "=r"(h) : "f"(v));
    float hf = __uint_as_float(h);
    asm("cvt.rna.tf32.f32 %0, %1;" : "=r"(lo) : "f"(v - hf));
    hi = h;
}

__device__ __forceinline__ void mma_tf32(float* c, const unsigned* a, const unsigned* b) {
    asm volatile(
        "mma.sync.aligned.m16n8k8.row.col.f32.tf32.tf32.f32 "
        "{%0,%1,%2,%3}, {%4,%5,%6,%7}, {%8,%9}, {%0,%1,%2,%3};\n"
        : "+f"(c[0]), "+f"(c[1]), "+f"(c[2]), "+f"(c[3])
        : "r"(a[0]), "r"(a[1]), "r"(a[2]), "r"(a[3]), "r"(b[0]), "r"(b[1]));
}

#define GBM 128
#define GBN 128
#define GBK 32
#define A_LD 36     // 32 + 4 pad  -> bank = 4*grp + tg, conflict-free
#define B_LD 136    // 128 + 8 pad -> bank = 8*tg + grp, conflict-free

__global__ __launch_bounds__(256, 2)
void gemm_3xtf32(const float* __restrict__ A, const float* __restrict__ Bm,
                 float* __restrict__ C, int M, int N, int K) {
    __shared__ __align__(16) float As[GBM][A_LD];   // [m][k]
    __shared__ __align__(16) float Bs[GBK][B_LD];   // [k][n]

    const int tid  = threadIdx.x;
    const int warp = tid >> 5;
    const int lane = tid & 31;
    const int grp  = lane >> 2;      // 0..7
    const int tg   = lane & 3;       // 0..3
    const int m_off = (warp >> 2) * 64;   // warp_m in {0,1}
    const int n_off = (warp & 3) * 32;    // warp_n in {0..3}
    const int bm = blockIdx.y * GBM;
    const int bn = blockIdx.x * GBN;

    float cc[4][4][4];
#pragma unroll
    for (int i = 0; i < 4; i++)
#pragma unroll
        for (int j = 0; j < 4; j++)
#pragma unroll
            for (int r = 0; r < 4; r++) cc[i][j][r] = 0.f;

    for (int k0 = 0; k0 < K; k0 += GBK) {
        // ---- stage A: 128 rows x 32 k, float4 per thread x4 ----
#pragma unroll
        for (int i = 0; i < 4; i++) {
            int f4 = tid + i * 256;
            int r  = f4 >> 3;
            int kq = (f4 & 7) << 2;
            float4 v = make_float4(0.f, 0.f, 0.f, 0.f);
            if (bm + r < M)
                v = *(const float4*)&A[(size_t)(bm + r) * K + k0 + kq];
            *(float4*)&As[r][kq] = v;
        }
        // ---- stage B: 32 k x 128 n ----
#pragma unroll
        for (int i = 0; i < 4; i++) {
            int f4 = tid + i * 256;
            int kr = f4 >> 5;
            int nq = (f4 & 31) << 2;
            *(float4*)&Bs[kr][nq] = *(const float4*)&Bm[(size_t)(k0 + kr) * N + bn + nq];
        }
        __syncthreads();

#pragma unroll
        for (int kk = 0; kk < 4; kk++) {
            const int ko = kk * 8;
            // B fragments (hi/lo) for all 4 n-subtiles
            unsigned bh[4][2], bl[4][2];
#pragma unroll
            for (int an = 0; an < 4; an++) {
                int c0 = n_off + an * 8 + grp;
                split_tf32(Bs[ko + tg][c0],     bh[an][0], bl[an][0]);
                split_tf32(Bs[ko + tg + 4][c0], bh[an][1], bl[an][1]);
            }
#pragma unroll
            for (int am = 0; am < 4; am++) {
                int r0 = m_off + am * 16 + grp;
                unsigned ah[4], al[4];
                split_tf32(As[r0][ko + tg],         ah[0], al[0]);
                split_tf32(As[r0 + 8][ko + tg],     ah[1], al[1]);
                split_tf32(As[r0][ko + tg + 4],     ah[2], al[2]);
                split_tf32(As[r0 + 8][ko + tg + 4], ah[3], al[3]);
#pragma unroll
                for (int an = 0; an < 4; an++) {
                    mma_tf32(cc[am][an], al, bh[an]);   // lo*hi
                    mma_tf32(cc[am][an], ah, bl[an]);   // hi*lo
                    mma_tf32(cc[am][an], ah, bh[an]);   // hi*hi
                }
            }
        }
        __syncthreads();
    }

    // ---- epilogue ----
#pragma unroll
    for (int am = 0; am < 4; am++) {
        int r0 = bm + m_off + am * 16 + grp;
#pragma unroll
        for (int an = 0; an < 4; an++) {
            int c0 = bn + n_off + an * 8 + 2 * tg;
            if (r0 < M)
                *(float2*)&C[(size_t)r0 * N + c0] = make_float2(cc[am][an][0], cc[am][an][1]);
            if (r0 + 8 < M)
                *(float2*)&C[(size_t)(r0 + 8) * N + c0] = make_float2(cc[am][an][2], cc[am][an][3]);
        }
    }
}

// ---------------------------------------------------------------------------
// Postprocess: tanh offsets + ref + clamp -> locs; shuffle softmax -> weights
// ---------------------------------------------------------------------------
__global__ void postproc(const float* __restrict__ offlog,
                         const float* __restrict__ attnlog,
                         const float* __restrict__ ref,
                         const float* __restrict__ boff,
                         const float* __restrict__ battn,
                         float* __restrict__ locs,
                         float* __restrict__ attnw) {
    const int bq = blockIdx.x;
    const int t = threadIdx.x;      // 0..255

    {
        float off = tanhf(offlog[(size_t)bq * 256 + t] + boff[t]);
        int rem = t & 31;
        int l = rem >> 3;
        int c = t & 1;
        float r = ref[(size_t)bq * (L_ * 2) + l * 2 + c];
        float v = r + off;
        v = fminf(fmaxf(v, -1.f), 1.f);
        locs[(size_t)bq * 256 + t] = v;
    }
    if (t < 128) {
        float v = attnlog[(size_t)bq * 128 + t] + battn[t];
        float mx = v;
#pragma unroll
        for (int d = 1; d < 16; d <<= 1)
            mx = fmaxf(mx, __shfl_xor_sync(0xffffffffu, mx, d));
        float e = __expf(v - mx);
        float s = e;
#pragma unroll
        for (int d = 1; d < 16; d <<= 1)
            s += __shfl_xor_sync(0xffffffffu, s, d);
        attnw[(size_t)bq * 128 + t] = e / s;
    }
}

// ---------------------------------------------------------------------------
// Deformable sampling: one warp per (bq, h); lane = channel d (0..31).
// ---------------------------------------------------------------------------
__global__ void sample_kernel(const float* __restrict__ vproj,
                              const float* __restrict__ locs,
                              const float* __restrict__ attnw,
                              const int* __restrict__ shapes,
                              float* __restrict__ acc) {
    const int gwarp = (blockIdx.x * blockDim.x + threadIdx.x) >> 5;
    const int lane = threadIdx.x & 31;
    if (gwarp >= BQ_ * H_) return;
    const int h = gwarp & 7;
    const int bq = gwarp >> 3;
    const int b = bq / Q_;

    const size_t locbase = (size_t)bq * 256 + h * 32;
    const size_t wbase = (size_t)bq * 128 + h * 16;
    const float* vb = vproj + (size_t)b * VLEN_ * E_ + h * HD_ + lane;

    float a = 0.f;
    int start = 0;
#pragma unroll
    for (int l = 0; l < L_; l++) {
        const int Hl = shapes[l * 2 + 0];
        const int Wl = shapes[l * 2 + 1];
        const float* p = vb + (size_t)start * E_;
#pragma unroll
        for (int k = 0; k < KP_; k++) {
            float w = __ldg(&attnw[wbase + l * 4 + k]);
            float lx = __ldg(&locs[locbase + (l * 4 + k) * 2 + 0]);
            float ly = __ldg(&locs[locbase + (l * 4 + k) * 2 + 1]);
            float x = (lx + 1.f) * 0.5f * (float)(Wl - 1);
            float y = (ly + 1.f) * 0.5f * (float)(Hl - 1);
            float x0f = floorf(x), y0f = floorf(y);
            float wx = x - x0f, wy = y - y0f;
            int x0 = min(max((int)x0f, 0), Wl - 1);
            int x1 = min(x0 + 1, Wl - 1);
            int y0 = min(max((int)y0f, 0), Hl - 1);
            int y1 = min(y0 + 1, Hl - 1);
            float v00 = p[(size_t)(y0 * Wl + x0) * E_];
            float v01 = p[(size_t)(y0 * Wl + x1) * E_];
            float v10 = p[(size_t)(y1 * Wl + x0) * E_];
            float v11 = p[(size_t)(y1 * Wl + x1) * E_];
            float v = (1.f - wy) * ((1.f - wx) * v00 + wx * v01)
                    + wy * ((1.f - wx) * v10 + wx * v11);
            a = fmaf(w, v, a);
        }
        start += Hl * Wl;
    }
    acc[(size_t)bq * E_ + h * HD_ + lane] = a;
}

// ---------------------------------------------------------------------------
extern "C" void kernel_launch(void* const* d_in, const int* in_sizes, int n_in,
                              void* d_out, int out_size) {
    const float* queries = (const float*)d_in[0];
    const float* ref     = (const float*)d_in[1];
    const float* value   = (const float*)d_in[2];
    const float* Wv      = (const float*)d_in[3];
    const float* Woff    = (const float*)d_in[4];
    const float* boff    = (const float*)d_in[5];
    const float* Wattn   = (const float*)d_in[6];
    const float* battn   = (const float*)d_in[7];
    const float* Wout    = (const float*)d_in[8];
    const int*   shapes  = (const int*)d_in[9];
    float* out = (float*)d_out;

    float *vproj, *offlog, *attnlog, *locs, *attnw, *acc;
    cudaGetSymbolAddress((void**)&vproj,  g_vproj);
    cudaGetSymbolAddress((void**)&offlog, g_offlog);
    cudaGetSymbolAddress((void**)&attnlog, g_attnlog);
    cudaGetSymbolAddress((void**)&locs,   g_locs);
    cudaGetSymbolAddress((void**)&attnw,  g_attnw);
    cudaGetSymbolAddress((void**)&acc,    g_acc);

    const int mblk = (BQ_ + GBM - 1) / GBM;   // 192 (BV_ == BQ_)

    gemm_3xtf32<<<dim3(E_ / GBN, mblk), 256>>>(value, Wv, vproj, BV_, E_, E_);
    gemm_3xtf32<<<dim3(256 / GBN, mblk), 256>>>(queries, Woff, offlog, BQ_, 256, E_);
    gemm_3xtf32<<<dim3(128 / GBN, mblk), 256>>>(queries, Wattn, attnlog, BQ_, 128, E_);
    postproc<<<BQ_, 256>>>(offlog, attnlog, ref, boff, battn, locs, attnw);
    {
        int total_threads = BQ_ * H_ * 32;
        sample_kernel<<<(total_threads + 255) / 256, 256>>>(vproj, locs, attnw, shapes, acc);
    }
    gemm_3xtf32<<<dim3(E_ / GBN, mblk), 256>>>(acc, Wout, out, BQ_, E_, E_);
}

// round 4
// speedup vs baseline: 2.3774x; 1.5677x over previous
#include <cuda_runtime.h>
#include <cuda_fp16.h>
#include <math.h>

// Problem constants (fixed by setup_inputs)
#define B_    2
#define Q_    12240
#define E_    256
#define H_    8
#define L_    4
#define KP_   4
#define HD_   32
#define VLEN_ 12240
#define BQ_   (B_ * Q_)      // 24480
#define BV_   (B_ * VLEN_)   // 24480

// Scratch (static __device__ — no allocation)
__device__ __half2 g_vproj_h[(size_t)BV_ * 128];   // (B, Vlen, 128 half2) 12.5 MB
__device__ float   g_locs[(size_t)BQ_ * 256];      // (bq, h,l,k,c)
__device__ float   g_attnw[(size_t)BQ_ * 128];     // (bq, h,l,k)
__device__ float   g_acc[(size_t)BQ_ * E_];        // sampled output

// ---------------------------------------------------------------------------
// 3xFP16 tensor-core GEMM: C = A * B (row-major fp32 in), fp32-class accuracy.
// v = hi + lo (both fp16, split at staging); accumulate lo*hi + hi*lo + hi*hi
// with mma.m16n8k16.f16.f32. Residual ~2^-22 (same as 3xTF32), 2x throughput.
// Block tile 128x128x32, 8 warps, warp tile 64x32.
// EPI: 0 = fp32 store, 1 = fp16 store, 2 = locs (tanh+ref+clamp),
//      3 = attn softmax (16-wide over head, via quad shuffles)
// Requires: K % 32 == 0, N % 128 == 0.
// ---------------------------------------------------------------------------
__device__ __forceinline__ void mma_f16(float* c, const unsigned* a, const unsigned* b) {
    asm volatile(
        "mma.sync.aligned.m16n8k16.row.col.f32.f16.f16.f32 "
        "{%0,%1,%2,%3}, {%4,%5,%6,%7}, {%8,%9}, {%0,%1,%2,%3};\n"
        : "+f"(c[0]), "+f"(c[1]), "+f"(c[2]), "+f"(c[3])
        : "r"(a[0]), "r"(a[1]), "r"(a[2]), "r"(a[3]), "r"(b[0]), "r"(b[1]));
}

__device__ __forceinline__ void split_h2(float x, float y, __half2& hi, __half2& lo) {
    __half hx = __float2half_rn(x), hy = __float2half_rn(y);
    hi = __halves2half2(hx, hy);
    lo = __halves2half2(__float2half_rn(x - __half2float(hx)),
                        __float2half_rn(y - __half2float(hy)));
}

#define GBM 128
#define GBN 128
#define GBK 32
#define A_K2  16    // k-pairs per tile
#define A_LDH 20    // 16 + 4 pad (half2) -> fragment banks 20*grp+tg all distinct
#define B_LDH 136   // 128 + 8 pad (half2) -> fragment banks 8*tg+grp all distinct

template<int EPI>
__global__ __launch_bounds__(256, 2)
void gemm_3xfp16(const float* __restrict__ A, const float* __restrict__ Bm,
                 void* __restrict__ Cv, int M, int N, int K,
                 const float* __restrict__ aux1, const float* __restrict__ aux2) {
    __shared__ __half2 As_hi[GBM][A_LDH], As_lo[GBM][A_LDH];   // 10 KB each
    __shared__ __half2 Bs_hi[A_K2][B_LDH], Bs_lo[A_K2][B_LDH]; // 8.5 KB each

    const int tid  = threadIdx.x;
    const int warp = tid >> 5;
    const int lane = tid & 31;
    const int grp  = lane >> 2;      // 0..7
    const int tg   = lane & 3;       // 0..3
    const int m_off = (warp >> 2) * 64;   // warp_m in {0,1}
    const int n_off = (warp & 3) * 32;    // warp_n in {0..3}
    const int bm = blockIdx.y * GBM;
    const int bn = blockIdx.x * GBN;

    float cc[4][4][4];
#pragma unroll
    for (int i = 0; i < 4; i++)
#pragma unroll
        for (int j = 0; j < 4; j++)
#pragma unroll
            for (int r = 0; r < 4; r++) cc[i][j][r] = 0.f;

    for (int k0 = 0; k0 < K; k0 += GBK) {
        // ---- stage A: 128 rows x 32 k; split to hi/lo half2 along k ----
#pragma unroll
        for (int i = 0; i < 4; i++) {
            int f4 = tid + i * 256;
            int r  = f4 >> 3;
            int kq = (f4 & 7) << 2;
            float4 v = make_float4(0.f, 0.f, 0.f, 0.f);
            if (bm + r < M)
                v = *(const float4*)&A[(size_t)(bm + r) * K + k0 + kq];
            __half2 h0, l0, h1, l1;
            split_h2(v.x, v.y, h0, l0);
            split_h2(v.z, v.w, h1, l1);
            int k2 = kq >> 1;
            As_hi[r][k2] = h0; As_hi[r][k2 + 1] = h1;
            As_lo[r][k2] = l0; As_lo[r][k2 + 1] = l1;
        }
        // ---- stage B: 32 k x 128 n; pack k-pairs into half2 ----
#pragma unroll
        for (int i = 0; i < 2; i++) {
            int u = tid + i * 256;
            int k2 = u >> 5;
            int n4 = (u & 31) << 2;
            const float* p0 = &Bm[(size_t)(k0 + 2 * k2) * N + bn + n4];
            float4 v0 = *(const float4*)p0;
            float4 v1 = *(const float4*)(p0 + N);
            __half2 h0, l0, h1, l1, h2v, l2v, h3, l3;
            split_h2(v0.x, v1.x, h0, l0);
            split_h2(v0.y, v1.y, h1, l1);
            split_h2(v0.z, v1.z, h2v, l2v);
            split_h2(v0.w, v1.w, h3, l3);
            Bs_hi[k2][n4] = h0; Bs_hi[k2][n4+1] = h1; Bs_hi[k2][n4+2] = h2v; Bs_hi[k2][n4+3] = h3;
            Bs_lo[k2][n4] = l0; Bs_lo[k2][n4+1] = l1; Bs_lo[k2][n4+2] = l2v; Bs_lo[k2][n4+3] = l3;
        }
        __syncthreads();

#pragma unroll
        for (int ch = 0; ch < 2; ch++) {
            const int ko2 = ch * 8;    // k-pair offset of this k16 chunk
            unsigned bh[4][2], bl[4][2];
#pragma unroll
            for (int an = 0; an < 4; an++) {
                int c0 = n_off + an * 8 + grp;
                bh[an][0] = *(const unsigned*)&Bs_hi[ko2 + tg][c0];
                bh[an][1] = *(const unsigned*)&Bs_hi[ko2 + tg + 4][c0];
                bl[an][0] = *(const unsigned*)&Bs_lo[ko2 + tg][c0];
                bl[an][1] = *(const unsigned*)&Bs_lo[ko2 + tg + 4][c0];
            }
#pragma unroll
            for (int am = 0; am < 4; am++) {
                int r0 = m_off + am * 16 + grp;
                unsigned ah[4], al[4];
                ah[0] = *(const unsigned*)&As_hi[r0][ko2 + tg];
                ah[1] = *(const unsigned*)&As_hi[r0 + 8][ko2 + tg];
                ah[2] = *(const unsigned*)&As_hi[r0][ko2 + tg + 4];
                ah[3] = *(const unsigned*)&As_hi[r0 + 8][ko2 + tg + 4];
                al[0] = *(const unsigned*)&As_lo[r0][ko2 + tg];
                al[1] = *(const unsigned*)&As_lo[r0 + 8][ko2 + tg];
                al[2] = *(const unsigned*)&As_lo[r0][ko2 + tg + 4];
                al[3] = *(const unsigned*)&As_lo[r0 + 8][ko2 + tg + 4];
#pragma unroll
                for (int an = 0; an < 4; an++) {
                    mma_f16(cc[am][an], al, bh[an]);   // lo*hi
                    mma_f16(cc[am][an], ah, bl[an]);   // hi*lo
                    mma_f16(cc[am][an], ah, bh[an]);   // hi*hi
                }
            }
        }
        __syncthreads();
    }

    // ======================= epilogues =======================
    if (EPI == 0) {
        float* C = (float*)Cv;
#pragma unroll
        for (int am = 0; am < 4; am++) {
            int r0 = bm + m_off + am * 16 + grp;
#pragma unroll
            for (int an = 0; an < 4; an++) {
                int c0 = bn + n_off + an * 8 + 2 * tg;
                if (r0 < M)
                    *(float2*)&C[(size_t)r0 * N + c0] = make_float2(cc[am][an][0], cc[am][an][1]);
                if (r0 + 8 < M)
                    *(float2*)&C[(size_t)(r0 + 8) * N + c0] = make_float2(cc[am][an][2], cc[am][an][3]);
            }
        }
    } else if (EPI == 1) {
        __half2* C = (__half2*)Cv;
        const int nh = N >> 1;
#pragma unroll
        for (int am = 0; am < 4; am++) {
            int r0 = bm + m_off + am * 16 + grp;
#pragma unroll
            for (int an = 0; an < 4; an++) {
                int c0 = bn + n_off + an * 8 + 2 * tg;
                if (r0 < M)
                    C[(size_t)r0 * nh + (c0 >> 1)] = __floats2half2_rn(cc[am][an][0], cc[am][an][1]);
                if (r0 + 8 < M)
                    C[(size_t)(r0 + 8) * nh + (c0 >> 1)] = __floats2half2_rn(cc[am][an][2], cc[am][an][3]);
            }
        }
    } else if (EPI == 2) {
        // locs = clamp(ref + tanh(logit + boff), -1, 1); aux1 = ref(B,Q,L,2), aux2 = boff
        float* C = (float*)Cv;
#pragma unroll
        for (int am = 0; am < 4; am++) {
#pragma unroll
            for (int rh = 0; rh < 2; rh++) {
                int row = bm + m_off + am * 16 + grp + rh * 8;
                if (row >= M) continue;
#pragma unroll
                for (int an = 0; an < 4; an++) {
                    int c0 = bn + n_off + an * 8 + 2 * tg;   // even -> c=0; c0+1 -> c=1
                    int l = (c0 >> 3) & 3;
                    float rx = __ldg(&aux1[(size_t)row * 8 + l * 2 + 0]);
                    float ry = __ldg(&aux1[(size_t)row * 8 + l * 2 + 1]);
                    float o0 = tanhf(cc[am][an][rh * 2 + 0] + __ldg(&aux2[c0]));
                    float o1 = tanhf(cc[am][an][rh * 2 + 1] + __ldg(&aux2[c0 + 1]));
                    float v0 = fminf(fmaxf(rx + o0, -1.f), 1.f);
                    float v1 = fminf(fmaxf(ry + o1, -1.f), 1.f);
                    *(float2*)&C[(size_t)row * N + c0] = make_float2(v0, v1);
                }
            }
        }
    } else {
        // EPI == 3: softmax over each 16-col head (cols of a head live in one
        // tg-quad: lanes 4*grp+{0..3}); aux1 = battn
        float* C = (float*)Cv;
#pragma unroll
        for (int am = 0; am < 4; am++) {
#pragma unroll
            for (int rh = 0; rh < 2; rh++) {
                int row = bm + m_off + am * 16 + grp + rh * 8;
#pragma unroll
                for (int hd2 = 0; hd2 < 2; hd2++) {
                    float v[4];
#pragma unroll
                    for (int q = 0; q < 4; q++) {
                        int an = hd2 * 2 + (q >> 1);
                        int s = q & 1;
                        int col = n_off + an * 8 + 2 * tg + s;
                        v[q] = cc[am][an][rh * 2 + s] + __ldg(&aux1[col]);
                    }
                    float m = fmaxf(fmaxf(v[0], v[1]), fmaxf(v[2], v[3]));
                    m = fmaxf(m, __shfl_xor_sync(0xffffffffu, m, 1));
                    m = fmaxf(m, __shfl_xor_sync(0xffffffffu, m, 2));
                    float e[4], sum = 0.f;
#pragma unroll
                    for (int q = 0; q < 4; q++) { e[q] = __expf(v[q] - m); sum += e[q]; }
                    sum += __shfl_xor_sync(0xffffffffu, sum, 1);
                    sum += __shfl_xor_sync(0xffffffffu, sum, 2);
                    float inv = 1.f / sum;
                    if (row < M) {
#pragma unroll
                        for (int a2 = 0; a2 < 2; a2++) {
                            int an = hd2 * 2 + a2;
                            int c0 = n_off + an * 8 + 2 * tg;
                            *(float2*)&C[(size_t)row * N + c0] =
                                make_float2(e[a2 * 2] * inv, e[a2 * 2 + 1] * inv);
                        }
                    }
                }
            }
        }
    }
}

// ---------------------------------------------------------------------------
// Deformable sampling (fp16 values): one warp covers 2 heads of one (b,q).
// Lane: sub = lane>>4 (head within pair), c2 = lane&15 (half2 channel pair).
// Corner fetch = 16 lanes x 4B = 64B coalesced per head group.
// ---------------------------------------------------------------------------
__global__ void sample_half(const __half2* __restrict__ vp,
                            const float* __restrict__ locs,
                            const float* __restrict__ attnw,
                            const int* __restrict__ shapes,
                            float* __restrict__ acc) {
    const int gwarp = (blockIdx.x * blockDim.x + threadIdx.x) >> 5;
    const int lane = threadIdx.x & 31;
    if (gwarp >= BQ_ * 4) return;
    const int hp = gwarp & 3;
    const int bq = gwarp >> 2;
    const int b = bq / Q_;
    const int sub = lane >> 4;
    const int c2 = lane & 15;
    const int h = hp * 2 + sub;

    const size_t locbase = (size_t)bq * 256 + h * 32;
    const size_t wbase = (size_t)bq * 128 + h * 16;
    const __half2* vb = vp + (size_t)b * VLEN_ * 128 + h * 16 + c2;

    float ax = 0.f, ay = 0.f;
    int start = 0;
#pragma unroll
    for (int l = 0; l < L_; l++) {
        const int Hl = shapes[l * 2 + 0];
        const int Wl = shapes[l * 2 + 1];
        const __half2* p = vb + (size_t)start * 128;
#pragma unroll
        for (int k = 0; k < KP_; k++) {
            float w = __ldg(&attnw[wbase + l * 4 + k]);
            float lx = __ldg(&locs[locbase + (l * 4 + k) * 2 + 0]);
            float ly = __ldg(&locs[locbase + (l * 4 + k) * 2 + 1]);
            float x = (lx + 1.f) * 0.5f * (float)(Wl - 1);
            float y = (ly + 1.f) * 0.5f * (float)(Hl - 1);
            float x0f = floorf(x), y0f = floorf(y);
            float wx = x - x0f, wy = y - y0f;
            int x0 = min(max((int)x0f, 0), Wl - 1);
            int x1 = min(x0 + 1, Wl - 1);
            int y0 = min(max((int)y0f, 0), Hl - 1);
            int y1 = min(y0 + 1, Hl - 1);
            float2 f00 = __half22float2(p[(size_t)(y0 * Wl + x0) * 128]);
            float2 f01 = __half22float2(p[(size_t)(y0 * Wl + x1) * 128]);
            float2 f10 = __half22float2(p[(size_t)(y1 * Wl + x0) * 128]);
            float2 f11 = __half22float2(p[(size_t)(y1 * Wl + x1) * 128]);
            float vx = (1.f - wy) * ((1.f - wx) * f00.x + wx * f01.x)
                     + wy * ((1.f - wx) * f10.x + wx * f11.x);
            float vy = (1.f - wy) * ((1.f - wx) * f00.y + wx * f01.y)
                     + wy * ((1.f - wx) * f10.y + wx * f11.y);
            ax = fmaf(w, vx, ax);
            ay = fmaf(w, vy, ay);
        }
        start += Hl * Wl;
    }
    *(float2*)&acc[(size_t)bq * 256 + h * 32 + c2 * 2] = make_float2(ax, ay);
}

// ---------------------------------------------------------------------------
extern "C" void kernel_launch(void* const* d_in, const int* in_sizes, int n_in,
                              void* d_out, int out_size) {
    const float* queries = (const float*)d_in[0];
    const float* ref     = (const float*)d_in[1];
    const float* value   = (const float*)d_in[2];
    const float* Wv      = (const float*)d_in[3];
    const float* Woff    = (const float*)d_in[4];
    const float* boff    = (const float*)d_in[5];
    const float* Wattn   = (const float*)d_in[6];
    const float* battn   = (const float*)d_in[7];
    const float* Wout    = (const float*)d_in[8];
    const int*   shapes  = (const int*)d_in[9];
    float* out = (float*)d_out;

    __half2* vproj;
    float *locs, *attnw, *acc;
    cudaGetSymbolAddress((void**)&vproj, g_vproj_h);
    cudaGetSymbolAddress((void**)&locs,  g_locs);
    cudaGetSymbolAddress((void**)&attnw, g_attnw);
    cudaGetSymbolAddress((void**)&acc,   g_acc);

    const int mblk = (BQ_ + GBM - 1) / GBM;   // 192 (BV_ == BQ_)

    // 1) value projection -> fp16 vproj
    gemm_3xfp16<1><<<dim3(E_ / GBN, mblk), 256>>>(value, Wv, vproj, BV_, E_, E_, nullptr, nullptr);
    // 2) offset logits -> fused tanh/ref/clamp -> locs
    gemm_3xfp16<2><<<dim3(256 / GBN, mblk), 256>>>(queries, Woff, locs, BQ_, 256, E_, ref, boff);
    // 3) attn logits -> fused softmax -> attnw
    gemm_3xfp16<3><<<dim3(128 / GBN, mblk), 256>>>(queries, Wattn, attnw, BQ_, 128, E_, battn, nullptr);
    // 4) deformable bilinear sampling (fp16 values, half2 lanes)
    {
        int total_threads = BQ_ * 4 * 32;
        sample_half<<<(total_threads + 255) / 256, 256>>>(vproj, locs, attnw, shapes, acc);
    }
    // 5) output projection -> d_out
    gemm_3xfp16<0><<<dim3(E_ / GBN, mblk), 256>>>(acc, Wout, out, BQ_, E_, E_, nullptr, nullptr);
}